// round 3
// baseline (speedup 1.0000x reference)
#include <cuda_runtime.h>

#define NN 32768
#define DD 256
#define KK 2048

#define BM 128
#define BN 128
#define BK 32
#define PAD 132   // BM + 4 padding floats, keeps float4 alignment

// Scratch (no device allocation allowed -> __device__ globals)
__device__ float  g_xnorm[NN];
__device__ float  g_cnorm[KK];
__device__ int    g_amin[NN];
__device__ double g_lsum;

// ---------------------------------------------------------------------------
// Row norms: s = sum(fl(x_d * x_d)), sequential add chain (mul then add, no fma)
// to mimic jnp.sum(x*x, axis=1).
// ---------------------------------------------------------------------------
__global__ void k_xnorm(const float* __restrict__ x) {
    int r = blockIdx.x * blockDim.x + threadIdx.x;
    if (r >= NN) return;
    const float4* p = (const float4*)(x + (size_t)r * DD);
    float s = 0.0f;
#pragma unroll
    for (int i = 0; i < DD / 4; ++i) {
        float4 v = p[i];
        s = __fadd_rn(s, __fmul_rn(v.x, v.x));
        s = __fadd_rn(s, __fmul_rn(v.y, v.y));
        s = __fadd_rn(s, __fmul_rn(v.z, v.z));
        s = __fadd_rn(s, __fmul_rn(v.w, v.w));
    }
    g_xnorm[r] = s;
}

__global__ void k_cnorm(const float* __restrict__ cb) {
    int r = blockIdx.x * blockDim.x + threadIdx.x;
    if (r >= KK) return;
    const float4* p = (const float4*)(cb + (size_t)r * DD);
    float s = 0.0f;
#pragma unroll
    for (int i = 0; i < DD / 4; ++i) {
        float4 v = p[i];
        s = __fadd_rn(s, __fmul_rn(v.x, v.x));
        s = __fadd_rn(s, __fmul_rn(v.y, v.y));
        s = __fadd_rn(s, __fmul_rn(v.z, v.z));
        s = __fadd_rn(s, __fmul_rn(v.w, v.w));
    }
    g_cnorm[r] = s;
}

__global__ void k_zero() {
    if (threadIdx.x == 0 && blockIdx.x == 0) g_lsum = 0.0;
}

// ---------------------------------------------------------------------------
// Fused distance GEMM + argmin.
// Each block: BM=128 rows, loops over 16 tiles of BN=128 codes.
// Thread (tx,ty) in 16x16 owns rows ty*8..+7 and cols tx*8..+7 (contiguous).
// dot accumulated with one sequential fp32 FMA chain per output, k ascending
// (bitwise match for a k-ordered FMA accumulation).
// dist = fl(fl(a + b) - 2*dot); argmin tie-break = lowest index.
// ---------------------------------------------------------------------------
__global__ __launch_bounds__(256) void k_dist(const float* __restrict__ x,
                                              const float* __restrict__ cb) {
    __shared__ float xs[BK][PAD];  // [k][row]
    __shared__ float cs[BK][PAD];  // [k][col]

    int tid = threadIdx.x;
    int tx = tid & 15;
    int ty = tid >> 4;
    int row0 = blockIdx.x * BM;

    float best[8];
    int   bidx[8];
    float areg[8];
#pragma unroll
    for (int i = 0; i < 8; ++i) {
        best[i] = 3.4e38f;
        bidx[i] = 0;
        areg[i] = g_xnorm[row0 + ty * 8 + i];
    }

    for (int ct = 0; ct < KK / BN; ++ct) {
        int col0 = ct * BN;

        float acc[8][8];
#pragma unroll
        for (int i = 0; i < 8; ++i)
#pragma unroll
            for (int j = 0; j < 8; ++j) acc[i][j] = 0.0f;

        for (int kb = 0; kb < DD / BK; ++kb) {
            __syncthreads();
            // Load x tile (128x32) and cb tile (128x32), transposed into smem.
#pragma unroll
            for (int it = 0; it < 4; ++it) {
                int idx = it * 256 + tid;  // 0..1023
                int r = idx >> 3;          // 0..127
                int c4 = idx & 7;          // 0..7
                float4 v = *(const float4*)&x[(size_t)(row0 + r) * DD + kb * BK + c4 * 4];
                xs[c4 * 4 + 0][r] = v.x;
                xs[c4 * 4 + 1][r] = v.y;
                xs[c4 * 4 + 2][r] = v.z;
                xs[c4 * 4 + 3][r] = v.w;
                float4 w = *(const float4*)&cb[(size_t)(col0 + r) * DD + kb * BK + c4 * 4];
                cs[c4 * 4 + 0][r] = w.x;
                cs[c4 * 4 + 1][r] = w.y;
                cs[c4 * 4 + 2][r] = w.z;
                cs[c4 * 4 + 3][r] = w.w;
            }
            __syncthreads();

#pragma unroll
            for (int k = 0; k < BK; ++k) {
                float xf[8], cf[8];
                *(float4*)&xf[0] = *(const float4*)&xs[k][ty * 8];
                *(float4*)&xf[4] = *(const float4*)&xs[k][ty * 8 + 4];
                *(float4*)&cf[0] = *(const float4*)&cs[k][tx * 8];
                *(float4*)&cf[4] = *(const float4*)&cs[k][tx * 8 + 4];
#pragma unroll
                for (int i = 0; i < 8; ++i)
#pragma unroll
                    for (int j = 0; j < 8; ++j)
                        acc[i][j] = __fmaf_rn(xf[i], cf[j], acc[i][j]);
            }
        }

        // Scores + running argmin (strict <, ascending index scan)
#pragma unroll
        for (int j = 0; j < 8; ++j) {
            int cidx = col0 + tx * 8 + j;
            float b = g_cnorm[cidx];
#pragma unroll
            for (int i = 0; i < 8; ++i) {
                float t = __fadd_rn(areg[i], b);
                float dist = __fadd_rn(t, -2.0f * acc[i][j]);
                if (dist < best[i]) { best[i] = dist; bidx[i] = cidx; }
            }
        }
    }

    // Cross-thread (over tx) reduction per row, lexicographic (val, idx)
    __syncthreads();
    float* redv = &xs[0][0];        // 128*16 floats fits in xs
    int*   redi = (int*)&cs[0][0];  // 128*16 ints fits in cs
#pragma unroll
    for (int i = 0; i < 8; ++i) {
        redv[(ty * 8 + i) * 16 + tx] = best[i];
        redi[(ty * 8 + i) * 16 + tx] = bidx[i];
    }
    __syncthreads();
    if (tid < BM) {
        float bv = redv[tid * 16];
        int bi = redi[tid * 16];
#pragma unroll
        for (int t = 1; t < 16; ++t) {
            float v = redv[tid * 16 + t];
            int iv = redi[tid * 16 + t];
            if (v < bv || (v == bv && iv < bi)) { bv = v; bi = iv; }
        }
        g_amin[row0 + tid] = bi;
    }
}

// ---------------------------------------------------------------------------
// Gather + straight-through output + loss partial sums.
// out = fl(x + fl(cb - x))  (replicates x + stop_grad(cb - x) in fp32)
// loss accumulator: sum of fl(x - cb)^2 in double.
// ---------------------------------------------------------------------------
__global__ __launch_bounds__(256) void k_gather(const float* __restrict__ x,
                                                const float* __restrict__ cb,
                                                float* __restrict__ out) {
    int tid = threadIdx.x;
    int row = blockIdx.x * 4 + (tid >> 6);
    int lane = tid & 63;
    int k = g_amin[row];

    float4 xv = *(const float4*)&x[(size_t)row * DD + lane * 4];
    float4 cv = *(const float4*)&cb[(size_t)k * DD + lane * 4];

    float4 o;
    o.x = __fadd_rn(xv.x, __fadd_rn(cv.x, -xv.x));
    o.y = __fadd_rn(xv.y, __fadd_rn(cv.y, -xv.y));
    o.z = __fadd_rn(xv.z, __fadd_rn(cv.z, -xv.z));
    o.w = __fadd_rn(xv.w, __fadd_rn(cv.w, -xv.w));
    *(float4*)&out[(size_t)row * DD + lane * 4] = o;

    float dx = __fadd_rn(xv.x, -cv.x);
    float dy = __fadd_rn(xv.y, -cv.y);
    float dz = __fadd_rn(xv.z, -cv.z);
    float dw = __fadd_rn(xv.w, -cv.w);
    double s = (double)(__fmul_rn(dx, dx)) + (double)(__fmul_rn(dy, dy)) +
               (double)(__fmul_rn(dz, dz)) + (double)(__fmul_rn(dw, dw));

    __shared__ double sred[256];
    sred[tid] = s;
    __syncthreads();
    for (int off = 128; off > 0; off >>= 1) {
        if (tid < off) sred[tid] += sred[tid + off];
        __syncthreads();
    }
    if (tid == 0) atomicAdd(&g_lsum, sred[0]);
}

__global__ void k_final(float* __restrict__ loss_loc) {
    // commit == embed numerically; loss = fl(fl(0.25*m) + m)
    float m = (float)(g_lsum / (double)((long long)NN * DD));
    *loss_loc = __fadd_rn(__fmul_rn(0.25f, m), m);
}

// ---------------------------------------------------------------------------
extern "C" void kernel_launch(void* const* d_in, const int* in_sizes, int n_in,
                              void* d_out, int out_size) {
    const float* x  = (const float*)d_in[0];   // [32768, 256]
    const float* cb = (const float*)d_in[1];   // [2048, 256]
    float* out = (float*)d_out;                // [32768*256] x_quantized + [1] loss

    k_xnorm<<<NN / 256, 256>>>(x);
    k_cnorm<<<KK / 256, 256>>>(cb);
    k_zero<<<1, 32>>>();
    k_dist<<<NN / BM, 256>>>(x, cb);
    k_gather<<<NN / 4, 256>>>(x, cb, out);
    if (out_size > NN * DD) {
        k_final<<<1, 1>>>(out + NN * DD);
    }
}

// round 4
// speedup vs baseline: 1.2680x; 1.2680x over previous
#include <cuda_runtime.h>

#define NN 32768
#define DD 256
#define KK 2048

#define BM 128
#define BN 128
#define BK 32
#define PAD 132   // row pitch in floats; 132*4=528 bytes ≡ 0 mod 16 (keeps float4 align)

// Dynamic smem: xs[256][PAD] + cs[32][PAD]
#define SMEM_FLOATS (DD * PAD + BK * PAD)
#define SMEM_BYTES  (SMEM_FLOATS * 4)

// Scratch (no device allocation allowed -> __device__ globals)
__device__ float  g_xnorm[NN];
__device__ float  g_cnorm[KK];
__device__ int    g_amin[NN];
__device__ double g_lsum;

// Packed fp32x2 helpers (Blackwell): each lane is an independent rn-rounded
// fp32 FMA -> bitwise identical to scalar FFMA per accumulator lane.
#define FMA2(d, a, b) asm("fma.rn.f32x2 %0, %1, %2, %0;" : "+l"(d) : "l"(a), "l"(b))
#define DUP2(d, s)    asm("mov.b64 %0, {%1, %1};" : "=l"(d) : "f"(s))

// ---------------------------------------------------------------------------
// Row norms: s = sum(fl(x_d * x_d)), sequential add chain (mul then add, no fma)
// ---------------------------------------------------------------------------
__global__ void k_xnorm(const float* __restrict__ x) {
    int r = blockIdx.x * blockDim.x + threadIdx.x;
    if (r >= NN) return;
    const float4* p = (const float4*)(x + (size_t)r * DD);
    float s = 0.0f;
#pragma unroll
    for (int i = 0; i < DD / 4; ++i) {
        float4 v = p[i];
        s = __fadd_rn(s, __fmul_rn(v.x, v.x));
        s = __fadd_rn(s, __fmul_rn(v.y, v.y));
        s = __fadd_rn(s, __fmul_rn(v.z, v.z));
        s = __fadd_rn(s, __fmul_rn(v.w, v.w));
    }
    g_xnorm[r] = s;
}

__global__ void k_cnorm(const float* __restrict__ cb) {
    int r = blockIdx.x * blockDim.x + threadIdx.x;
    if (r >= KK) return;
    const float4* p = (const float4*)(cb + (size_t)r * DD);
    float s = 0.0f;
#pragma unroll
    for (int i = 0; i < DD / 4; ++i) {
        float4 v = p[i];
        s = __fadd_rn(s, __fmul_rn(v.x, v.x));
        s = __fadd_rn(s, __fmul_rn(v.y, v.y));
        s = __fadd_rn(s, __fmul_rn(v.z, v.z));
        s = __fadd_rn(s, __fmul_rn(v.w, v.w));
    }
    g_cnorm[r] = s;
}

__global__ void k_zero() {
    if (threadIdx.x == 0 && blockIdx.x == 0) g_lsum = 0.0;
}

// ---------------------------------------------------------------------------
// Fused distance GEMM + argmin, packed f32x2 FMA.
// Block: BM=128 rows. Full x slab (128 x 256, transposed) staged in smem ONCE.
// Loop 16 column-tiles of BN=128 codes; cs tile (32 x 128 transposed) per kb.
// Thread (tx,ty) in 16x16 owns rows ty*8..+7, cols tx*8..+7.
// acc2[ip][j]: lanes (row 2ip, row 2ip+1) x col j. 'a' pairs come straight
// from the xs float4 (reinterpret), 'b' is a per-col broadcast dup (ALU pipe).
// Accumulation stays one sequential k-ascending chain per output lane ->
// bitwise identical to the scalar-FFMA round-3 kernel.
// ---------------------------------------------------------------------------
__global__ __launch_bounds__(256) void k_dist(const float* __restrict__ x,
                                              const float* __restrict__ cb) {
    extern __shared__ float smem[];
    float* xs = smem;             // [DD][PAD] : xs[k*PAD + r] = x[row0+r][k]
    float* cs = smem + DD * PAD;  // [BK][PAD] : cs[k*PAD + c] = cb[col0+c][kb*BK+k]

    int tid = threadIdx.x;
    int tx = tid & 15;
    int ty = tid >> 4;
    int row0 = blockIdx.x * BM;

    // ---- one-time load of the full x slab, transposed ----
#pragma unroll 4
    for (int it = 0; it < 32; ++it) {
        int idx = it * 256 + tid;   // 0..8191
        int r = idx & 127;
        int c4 = idx >> 7;          // 0..63
        float4 v = *(const float4*)&x[(size_t)(row0 + r) * DD + c4 * 4];
        xs[(c4 * 4 + 0) * PAD + r] = v.x;
        xs[(c4 * 4 + 1) * PAD + r] = v.y;
        xs[(c4 * 4 + 2) * PAD + r] = v.z;
        xs[(c4 * 4 + 3) * PAD + r] = v.w;
    }

    float best[8];
    int   bidx[8];
    float areg[8];
#pragma unroll
    for (int i = 0; i < 8; ++i) {
        best[i] = 3.4e38f;
        bidx[i] = 0;
        areg[i] = g_xnorm[row0 + ty * 8 + i];
    }

    for (int ct = 0; ct < KK / BN; ++ct) {
        int col0 = ct * BN;

        unsigned long long acc2[4][8];
#pragma unroll
        for (int ip = 0; ip < 4; ++ip)
#pragma unroll
            for (int j = 0; j < 8; ++j) acc2[ip][j] = 0ULL;

        for (int kb = 0; kb < DD / BK; ++kb) {
            __syncthreads();  // also orders xs stores before first reads
            // stage cb tile (128 cols x 32 k), transposed
#pragma unroll
            for (int it = 0; it < 4; ++it) {
                int idx = it * 256 + tid;  // 0..1023
                int c = idx & 127;
                int c4 = idx >> 7;         // 0..7
                float4 w = *(const float4*)&cb[(size_t)(col0 + c) * DD + kb * BK + c4 * 4];
                cs[(c4 * 4 + 0) * PAD + c] = w.x;
                cs[(c4 * 4 + 1) * PAD + c] = w.y;
                cs[(c4 * 4 + 2) * PAD + c] = w.z;
                cs[(c4 * 4 + 3) * PAD + c] = w.w;
            }
            __syncthreads();

#pragma unroll
            for (int k = 0; k < BK; ++k) {
                const float* xrow = &xs[(kb * BK + k) * PAD + ty * 8];
                ulonglong2 av01 = *(const ulonglong2*)xrow;        // (r0,r1),(r2,r3)
                ulonglong2 av23 = *(const ulonglong2*)(xrow + 4);  // (r4,r5),(r6,r7)
                unsigned long long a2[4] = {av01.x, av01.y, av23.x, av23.y};

                const float* crow = &cs[k * PAD + tx * 8];
                float4 c0 = *(const float4*)crow;
                float4 c1 = *(const float4*)(crow + 4);
                unsigned long long b2[8];
                DUP2(b2[0], c0.x); DUP2(b2[1], c0.y);
                DUP2(b2[2], c0.z); DUP2(b2[3], c0.w);
                DUP2(b2[4], c1.x); DUP2(b2[5], c1.y);
                DUP2(b2[6], c1.z); DUP2(b2[7], c1.w);

#pragma unroll
                for (int ip = 0; ip < 4; ++ip)
#pragma unroll
                    for (int j = 0; j < 8; ++j)
                        FMA2(acc2[ip][j], a2[ip], b2[j]);
            }
        }

        // Scores + running argmin (strict <, ascending index scan)
#pragma unroll
        for (int j = 0; j < 8; ++j) {
            int cidx = col0 + tx * 8 + j;
            float b = g_cnorm[cidx];
#pragma unroll
            for (int ip = 0; ip < 4; ++ip) {
                union { unsigned long long u; float2 f; } t;
                t.u = acc2[ip][j];
                int i0 = 2 * ip, i1 = 2 * ip + 1;
                float s0 = __fadd_rn(areg[i0], b);
                float d0 = __fadd_rn(s0, -2.0f * t.f.x);
                if (d0 < best[i0]) { best[i0] = d0; bidx[i0] = cidx; }
                float s1 = __fadd_rn(areg[i1], b);
                float d1 = __fadd_rn(s1, -2.0f * t.f.y);
                if (d1 < best[i1]) { best[i1] = d1; bidx[i1] = cidx; }
            }
        }
    }

    // Cross-thread (over tx) reduction per row, lexicographic (val, idx)
    __syncthreads();
    float* redv = cs;                 // 2048 floats (cs region has 4224)
    int*   redi = (int*)(cs + 2048);  // 2048 ints
#pragma unroll
    for (int i = 0; i < 8; ++i) {
        redv[(ty * 8 + i) * 16 + tx] = best[i];
        redi[(ty * 8 + i) * 16 + tx] = bidx[i];
    }
    __syncthreads();
    if (tid < BM) {
        float bv = redv[tid * 16];
        int bi = redi[tid * 16];
#pragma unroll
        for (int t = 1; t < 16; ++t) {
            float v = redv[tid * 16 + t];
            int iv = redi[tid * 16 + t];
            if (v < bv || (v == bv && iv < bi)) { bv = v; bi = iv; }
        }
        g_amin[row0 + tid] = bi;
    }
}

// ---------------------------------------------------------------------------
// Gather + straight-through output + loss partial sums.
// ---------------------------------------------------------------------------
__global__ __launch_bounds__(256) void k_gather(const float* __restrict__ x,
                                                const float* __restrict__ cb,
                                                float* __restrict__ out) {
    int tid = threadIdx.x;
    int row = blockIdx.x * 4 + (tid >> 6);
    int lane = tid & 63;
    int k = g_amin[row];

    float4 xv = *(const float4*)&x[(size_t)row * DD + lane * 4];
    float4 cv = *(const float4*)&cb[(size_t)k * DD + lane * 4];

    float4 o;
    o.x = __fadd_rn(xv.x, __fadd_rn(cv.x, -xv.x));
    o.y = __fadd_rn(xv.y, __fadd_rn(cv.y, -xv.y));
    o.z = __fadd_rn(xv.z, __fadd_rn(cv.z, -xv.z));
    o.w = __fadd_rn(xv.w, __fadd_rn(cv.w, -xv.w));
    *(float4*)&out[(size_t)row * DD + lane * 4] = o;

    float dx = __fadd_rn(xv.x, -cv.x);
    float dy = __fadd_rn(xv.y, -cv.y);
    float dz = __fadd_rn(xv.z, -cv.z);
    float dw = __fadd_rn(xv.w, -cv.w);
    double s = (double)(__fmul_rn(dx, dx)) + (double)(__fmul_rn(dy, dy)) +
               (double)(__fmul_rn(dz, dz)) + (double)(__fmul_rn(dw, dw));

    __shared__ double sred[256];
    sred[tid] = s;
    __syncthreads();
    for (int off = 128; off > 0; off >>= 1) {
        if (tid < off) sred[tid] += sred[tid + off];
        __syncthreads();
    }
    if (tid == 0) atomicAdd(&g_lsum, sred[0]);
}

__global__ void k_final(float* __restrict__ loss_loc) {
    float m = (float)(g_lsum / (double)((long long)NN * DD));
    *loss_loc = __fadd_rn(__fmul_rn(0.25f, m), m);
}

// ---------------------------------------------------------------------------
extern "C" void kernel_launch(void* const* d_in, const int* in_sizes, int n_in,
                              void* d_out, int out_size) {
    const float* x  = (const float*)d_in[0];   // [32768, 256]
    const float* cb = (const float*)d_in[1];   // [2048, 256]
    float* out = (float*)d_out;                // [32768*256] x_quantized + [1] loss

    // Not a stream op; safe under graph capture. Idempotent.
    cudaFuncSetAttribute(k_dist, cudaFuncAttributeMaxDynamicSharedMemorySize,
                         SMEM_BYTES);

    k_xnorm<<<NN / 256, 256>>>(x);
    k_cnorm<<<KK / 256, 256>>>(cb);
    k_zero<<<1, 32>>>();
    k_dist<<<NN / BM, 256, SMEM_BYTES>>>(x, cb);
    k_gather<<<NN / 4, 256>>>(x, cb, out);
    if (out_size > NN * DD) {
        k_final<<<1, 1>>>(out + NN * DD);
    }
}

// round 6
// speedup vs baseline: 1.3362x; 1.0538x over previous
#include <cuda_runtime.h>
#include <cstdint>

#define NN 32768
#define DD 256
#define KK 2048

#define BM 128
#define BN 128
#define BK 32
#define PAD 132   // row pitch in floats; 132*4=528 ≡ 0 mod 16 (float4-aligned rows)

// Scratch (no device allocation allowed -> __device__ globals)
__device__ float  g_xnorm[NN];
__device__ float  g_cnorm[KK];
__device__ int    g_amin[NN];
__device__ double g_lsum;

// Packed fp32x2 helpers (Blackwell): each lane is an independent rn-rounded
// fp32 FMA -> bitwise identical to scalar FFMA per accumulator lane.
#define FMA2(d, a, b) asm("fma.rn.f32x2 %0, %1, %2, %0;" : "+l"(d) : "l"(a), "l"(b))
#define DUP2(d, s)    asm("mov.b64 %0, {%1, %1};" : "=l"(d) : "f"(s))

// ---------------------------------------------------------------------------
// Row norms: s = sum(fl(x_d * x_d)), sequential add chain (mul then add, no fma)
// ---------------------------------------------------------------------------
__global__ void k_xnorm(const float* __restrict__ x) {
    int r = blockIdx.x * blockDim.x + threadIdx.x;
    if (r >= NN) return;
    const float4* p = (const float4*)(x + (size_t)r * DD);
    float s = 0.0f;
#pragma unroll
    for (int i = 0; i < DD / 4; ++i) {
        float4 v = p[i];
        s = __fadd_rn(s, __fmul_rn(v.x, v.x));
        s = __fadd_rn(s, __fmul_rn(v.y, v.y));
        s = __fadd_rn(s, __fmul_rn(v.z, v.z));
        s = __fadd_rn(s, __fmul_rn(v.w, v.w));
    }
    g_xnorm[r] = s;
}

__global__ void k_cnorm(const float* __restrict__ cb) {
    int r = blockIdx.x * blockDim.x + threadIdx.x;
    if (r >= KK) return;
    const float4* p = (const float4*)(cb + (size_t)r * DD);
    float s = 0.0f;
#pragma unroll
    for (int i = 0; i < DD / 4; ++i) {
        float4 v = p[i];
        s = __fadd_rn(s, __fmul_rn(v.x, v.x));
        s = __fadd_rn(s, __fmul_rn(v.y, v.y));
        s = __fadd_rn(s, __fmul_rn(v.z, v.z));
        s = __fadd_rn(s, __fmul_rn(v.w, v.w));
    }
    g_cnorm[r] = s;
}

__global__ void k_zero() {
    if (threadIdx.x == 0 && blockIdx.x == 0) g_lsum = 0.0;
}

// ---------------------------------------------------------------------------
// Fused distance GEMM + argmin, packed f32x2 FMA, 34 KB smem so TWO CTAs
// fit per SM (the round-4 x-slab version was 152 KB -> 1 CTA -> 12.5% occ,
// issue 33.6%; this trades cheap L2 re-reads for 2x warp parallelism).
// Thread (tx,ty) in 16x16 owns rows ty*8..+7 and cols tx*8..+7.
// Accumulation: one sequential k-ascending rn FMA chain per output lane ->
// bitwise identical picks to the round-3/4 passing kernels.
// ---------------------------------------------------------------------------
__global__ __launch_bounds__(256, 2) void k_dist(const float* __restrict__ x,
                                                 const float* __restrict__ cb) {
    __shared__ float xs[BK][PAD];  // [k][row]
    __shared__ float cs[BK][PAD];  // [k][col]

    int tid = threadIdx.x;
    int tx = tid & 15;
    int ty = tid >> 4;
    int row0 = blockIdx.x * BM;

    float best[8];
    int   bidx[8];
    float areg[8];
#pragma unroll
    for (int i = 0; i < 8; ++i) {
        best[i] = 3.4e38f;
        bidx[i] = 0;
        areg[i] = g_xnorm[row0 + ty * 8 + i];
    }

    for (int ct = 0; ct < KK / BN; ++ct) {
        int col0 = ct * BN;

        unsigned long long acc2[4][8];
#pragma unroll
        for (int ip = 0; ip < 4; ++ip)
#pragma unroll
            for (int j = 0; j < 8; ++j) acc2[ip][j] = 0ULL;

        for (int kb = 0; kb < DD / BK; ++kb) {
            __syncthreads();
            // Stage x tile (128x32) and cb tile (128x32), transposed.
#pragma unroll
            for (int it = 0; it < 4; ++it) {
                int idx = it * 256 + tid;  // 0..1023
                int r = idx >> 3;          // 0..127
                int c4 = idx & 7;          // 0..7
                float4 v = *(const float4*)&x[(size_t)(row0 + r) * DD + kb * BK + c4 * 4];
                xs[c4 * 4 + 0][r] = v.x;
                xs[c4 * 4 + 1][r] = v.y;
                xs[c4 * 4 + 2][r] = v.z;
                xs[c4 * 4 + 3][r] = v.w;
                float4 w = *(const float4*)&cb[(size_t)(col0 + r) * DD + kb * BK + c4 * 4];
                cs[c4 * 4 + 0][r] = w.x;
                cs[c4 * 4 + 1][r] = w.y;
                cs[c4 * 4 + 2][r] = w.z;
                cs[c4 * 4 + 3][r] = w.w;
            }
            __syncthreads();

#pragma unroll
            for (int k = 0; k < BK; ++k) {
                const float* xrow = &xs[k][ty * 8];
                ulonglong2 av01 = *(const ulonglong2*)xrow;        // (r0,r1),(r2,r3)
                ulonglong2 av23 = *(const ulonglong2*)(xrow + 4);  // (r4,r5),(r6,r7)
                unsigned long long a2[4] = {av01.x, av01.y, av23.x, av23.y};

                const float* crow = &cs[k][tx * 8];
                float4 c0 = *(const float4*)crow;
                float4 c1 = *(const float4*)(crow + 4);
                unsigned long long b2[8];
                DUP2(b2[0], c0.x); DUP2(b2[1], c0.y);
                DUP2(b2[2], c0.z); DUP2(b2[3], c0.w);
                DUP2(b2[4], c1.x); DUP2(b2[5], c1.y);
                DUP2(b2[6], c1.z); DUP2(b2[7], c1.w);

#pragma unroll
                for (int ip = 0; ip < 4; ++ip)
#pragma unroll
                    for (int j = 0; j < 8; ++j)
                        FMA2(acc2[ip][j], a2[ip], b2[j]);
            }
        }

        // Scores + running argmin (strict <, ascending index scan)
#pragma unroll
        for (int j = 0; j < 8; ++j) {
            int cidx = col0 + tx * 8 + j;
            float b = g_cnorm[cidx];
#pragma unroll
            for (int ip = 0; ip < 4; ++ip) {
                union { unsigned long long u; float2 f; } t;
                t.u = acc2[ip][j];
                int i0 = 2 * ip, i1 = 2 * ip + 1;
                float s0 = __fadd_rn(areg[i0], b);
                float d0 = __fadd_rn(s0, -2.0f * t.f.x);
                if (d0 < best[i0]) { best[i0] = d0; bidx[i0] = cidx; }
                float s1 = __fadd_rn(areg[i1], b);
                float d1 = __fadd_rn(s1, -2.0f * t.f.y);
                if (d1 < best[i1]) { best[i1] = d1; bidx[i1] = cidx; }
            }
        }
    }

    // Cross-thread (over tx) reduction per row, lexicographic (val, idx)
    __syncthreads();
    float* redv = &xs[0][0];        // 2048 floats fits in xs (BK*PAD = 4224)
    int*   redi = (int*)&cs[0][0];  // 2048 ints fits in cs
#pragma unroll
    for (int i = 0; i < 8; ++i) {
        redv[(ty * 8 + i) * 16 + tx] = best[i];
        redi[(ty * 8 + i) * 16 + tx] = bidx[i];
    }
    __syncthreads();
    if (tid < BM) {
        float bv = redv[tid * 16];
        int bi = redi[tid * 16];
#pragma unroll
        for (int t = 1; t < 16; ++t) {
            float v = redv[tid * 16 + t];
            int iv = redi[tid * 16 + t];
            if (v < bv || (v == bv && iv < bi)) { bv = v; bi = iv; }
        }
        g_amin[row0 + tid] = bi;
    }
}

// ---------------------------------------------------------------------------
// Gather + straight-through output + loss partial sums.
// ---------------------------------------------------------------------------
__global__ __launch_bounds__(256) void k_gather(const float* __restrict__ x,
                                                const float* __restrict__ cb,
                                                float* __restrict__ out) {
    int tid = threadIdx.x;
    int row = blockIdx.x * 4 + (tid >> 6);
    int lane = tid & 63;
    int k = g_amin[row];

    float4 xv = *(const float4*)&x[(size_t)row * DD + lane * 4];
    float4 cv = *(const float4*)&cb[(size_t)k * DD + lane * 4];

    float4 o;
    o.x = __fadd_rn(xv.x, __fadd_rn(cv.x, -xv.x));
    o.y = __fadd_rn(xv.y, __fadd_rn(cv.y, -xv.y));
    o.z = __fadd_rn(xv.z, __fadd_rn(cv.z, -xv.z));
    o.w = __fadd_rn(xv.w, __fadd_rn(cv.w, -xv.w));
    *(float4*)&out[(size_t)row * DD + lane * 4] = o;

    float dx = __fadd_rn(xv.x, -cv.x);
    float dy = __fadd_rn(xv.y, -cv.y);
    float dz = __fadd_rn(xv.z, -cv.z);
    float dw = __fadd_rn(xv.w, -cv.w);
    double s = (double)(__fmul_rn(dx, dx)) + (double)(__fmul_rn(dy, dy)) +
               (double)(__fmul_rn(dz, dz)) + (double)(__fmul_rn(dw, dw));

    __shared__ double sred[256];
    sred[tid] = s;
    __syncthreads();
    for (int off = 128; off > 0; off >>= 1) {
        if (tid < off) sred[tid] += sred[tid + off];
        __syncthreads();
    }
    if (tid == 0) atomicAdd(&g_lsum, sred[0]);
}

__global__ void k_final(float* __restrict__ loss_loc) {
    float m = (float)(g_lsum / (double)((long long)NN * DD));
    *loss_loc = __fadd_rn(__fmul_rn(0.25f, m), m);
}

// ---------------------------------------------------------------------------
extern "C" void kernel_launch(void* const* d_in, const int* in_sizes, int n_in,
                              void* d_out, int out_size) {
    const float* x  = (const float*)d_in[0];   // [32768, 256]
    const float* cb = (const float*)d_in[1];   // [2048, 256]
    float* out = (float*)d_out;                // [32768*256] x_quantized + [1] loss

    k_xnorm<<<NN / 256, 256>>>(x);
    k_cnorm<<<KK / 256, 256>>>(cb);
    k_zero<<<1, 32>>>();
    k_dist<<<NN / BM, 256>>>(x, cb);
    k_gather<<<NN / 4, 256>>>(x, cb, out);
    if (out_size > NN * DD) {
        k_final<<<1, 1>>>(out + NN * DD);
    }
}

// round 7
// speedup vs baseline: 1.4295x; 1.0698x over previous
#include <cuda_runtime.h>
#include <cstdint>

#define NN 32768
#define DD 256
#define KK 2048

#define BM 128
#define BN 128
#define BK 32
#define PAD 132   // row pitch in floats; 132*4=528 ≡ 0 mod 16 (float4-aligned rows)

// Scratch (no device allocation allowed -> __device__ globals)
__device__ float  g_xnorm[NN];
__device__ float  g_cnorm[KK];
__device__ int    g_amin[NN];
__device__ double g_lsum;

// Packed fp32x2 helpers (Blackwell): each lane is an independent rn-rounded
// fp32 FMA -> bitwise identical to scalar FFMA per accumulator lane.
#define FMA2(d, a, b) asm("fma.rn.f32x2 %0, %1, %2, %0;" : "+l"(d) : "l"(a), "l"(b))
#define DUP2(d, s)    asm("mov.b64 %0, {%1, %1};" : "=l"(d) : "f"(s))

// ---------------------------------------------------------------------------
// Row norms: s = sum(fl(x_d * x_d)), sequential add chain (mul then add, no fma)
// ---------------------------------------------------------------------------
__global__ void k_xnorm(const float* __restrict__ x) {
    int r = blockIdx.x * blockDim.x + threadIdx.x;
    if (r >= NN) return;
    const float4* p = (const float4*)(x + (size_t)r * DD);
    float s = 0.0f;
#pragma unroll
    for (int i = 0; i < DD / 4; ++i) {
        float4 v = p[i];
        s = __fadd_rn(s, __fmul_rn(v.x, v.x));
        s = __fadd_rn(s, __fmul_rn(v.y, v.y));
        s = __fadd_rn(s, __fmul_rn(v.z, v.z));
        s = __fadd_rn(s, __fmul_rn(v.w, v.w));
    }
    g_xnorm[r] = s;
}

__global__ void k_cnorm(const float* __restrict__ cb) {
    int r = blockIdx.x * blockDim.x + threadIdx.x;
    if (r >= KK) return;
    const float4* p = (const float4*)(cb + (size_t)r * DD);
    float s = 0.0f;
#pragma unroll
    for (int i = 0; i < DD / 4; ++i) {
        float4 v = p[i];
        s = __fadd_rn(s, __fmul_rn(v.x, v.x));
        s = __fadd_rn(s, __fmul_rn(v.y, v.y));
        s = __fadd_rn(s, __fmul_rn(v.z, v.z));
        s = __fadd_rn(s, __fmul_rn(v.w, v.w));
    }
    g_cnorm[r] = s;
}

__global__ void k_zero() {
    if (threadIdx.x == 0 && blockIdx.x == 0) g_lsum = 0.0;
}

// ---------------------------------------------------------------------------
// Fused distance GEMM + argmin, packed f32x2 FMA, 2 CTAs/SM.
// Round-6 ncu showed L1tex at 79.8% from 4-way bank conflicts on the cs
// loads (per-thread column base tx*8 -> 32B stride). Fix: thread tx owns
// cols {tx*4..+3} and {64+tx*4..+3}; each cs float4 load is then a clean
// contiguous 256B warp access (2 wavefronts, conflict-free, ty-pair
// broadcast). Same FMA2 chains -> bitwise-identical distances; per-thread
// scan still ascending-index, so picks are unchanged.
// ---------------------------------------------------------------------------
__global__ __launch_bounds__(256, 2) void k_dist(const float* __restrict__ x,
                                                 const float* __restrict__ cb) {
    __shared__ float xs[BK][PAD];  // [k][row]
    __shared__ float cs[BK][PAD];  // [k][col]

    int tid = threadIdx.x;
    int tx = tid & 15;
    int ty = tid >> 4;
    int row0 = blockIdx.x * BM;

    float best[8];
    int   bidx[8];
    float areg[8];
#pragma unroll
    for (int i = 0; i < 8; ++i) {
        best[i] = 3.4e38f;
        bidx[i] = 0;
        areg[i] = g_xnorm[row0 + ty * 8 + i];
    }

    for (int ct = 0; ct < KK / BN; ++ct) {
        int col0 = ct * BN;

        unsigned long long acc2[4][8];
#pragma unroll
        for (int ip = 0; ip < 4; ++ip)
#pragma unroll
            for (int j = 0; j < 8; ++j) acc2[ip][j] = 0ULL;

        for (int kb = 0; kb < DD / BK; ++kb) {
            __syncthreads();
            // Stage x tile (128x32) and cb tile (128x32), transposed.
#pragma unroll
            for (int it = 0; it < 4; ++it) {
                int idx = it * 256 + tid;  // 0..1023
                int r = idx >> 3;          // 0..127
                int c4 = idx & 7;          // 0..7
                float4 v = *(const float4*)&x[(size_t)(row0 + r) * DD + kb * BK + c4 * 4];
                xs[c4 * 4 + 0][r] = v.x;
                xs[c4 * 4 + 1][r] = v.y;
                xs[c4 * 4 + 2][r] = v.z;
                xs[c4 * 4 + 3][r] = v.w;
                float4 w = *(const float4*)&cb[(size_t)(col0 + r) * DD + kb * BK + c4 * 4];
                cs[c4 * 4 + 0][r] = w.x;
                cs[c4 * 4 + 1][r] = w.y;
                cs[c4 * 4 + 2][r] = w.z;
                cs[c4 * 4 + 3][r] = w.w;
            }
            __syncthreads();

#pragma unroll
            for (int k = 0; k < BK; ++k) {
                const float* xrow = &xs[k][ty * 8];
                ulonglong2 av01 = *(const ulonglong2*)xrow;        // (r0,r1),(r2,r3)
                ulonglong2 av23 = *(const ulonglong2*)(xrow + 4);  // (r4,r5),(r6,r7)
                unsigned long long a2[4] = {av01.x, av01.y, av23.x, av23.y};

                // cols {tx*4..+3} and {64+tx*4..+3}: contiguous 256B warp
                // accesses, conflict-free.
                float4 c0 = *(const float4*)&cs[k][tx * 4];
                float4 c1 = *(const float4*)&cs[k][64 + tx * 4];
                unsigned long long b2[8];
                DUP2(b2[0], c0.x); DUP2(b2[1], c0.y);
                DUP2(b2[2], c0.z); DUP2(b2[3], c0.w);
                DUP2(b2[4], c1.x); DUP2(b2[5], c1.y);
                DUP2(b2[6], c1.z); DUP2(b2[7], c1.w);

#pragma unroll
                for (int ip = 0; ip < 4; ++ip)
#pragma unroll
                    for (int j = 0; j < 8; ++j)
                        FMA2(acc2[ip][j], a2[ip], b2[j]);
            }
        }

        // Scores + running argmin (strict <, ascending index scan per thread)
#pragma unroll
        for (int j = 0; j < 8; ++j) {
            int cidx = (j < 4) ? (col0 + tx * 4 + j)
                               : (col0 + 64 + tx * 4 + (j - 4));
            float b = g_cnorm[cidx];
#pragma unroll
            for (int ip = 0; ip < 4; ++ip) {
                union { unsigned long long u; float2 f; } t;
                t.u = acc2[ip][j];
                int i0 = 2 * ip, i1 = 2 * ip + 1;
                float s0 = __fadd_rn(areg[i0], b);
                float d0 = __fadd_rn(s0, -2.0f * t.f.x);
                if (d0 < best[i0]) { best[i0] = d0; bidx[i0] = cidx; }
                float s1 = __fadd_rn(areg[i1], b);
                float d1 = __fadd_rn(s1, -2.0f * t.f.y);
                if (d1 < best[i1]) { best[i1] = d1; bidx[i1] = cidx; }
            }
        }
    }

    // Cross-thread (over tx) reduction per row, lexicographic (val, idx)
    __syncthreads();
    float* redv = &xs[0][0];        // 2048 floats fits in xs (BK*PAD = 4224)
    int*   redi = (int*)&cs[0][0];  // 2048 ints fits in cs
#pragma unroll
    for (int i = 0; i < 8; ++i) {
        redv[(ty * 8 + i) * 16 + tx] = best[i];
        redi[(ty * 8 + i) * 16 + tx] = bidx[i];
    }
    __syncthreads();
    if (tid < BM) {
        float bv = redv[tid * 16];
        int bi = redi[tid * 16];
#pragma unroll
        for (int t = 1; t < 16; ++t) {
            float v = redv[tid * 16 + t];
            int iv = redi[tid * 16 + t];
            if (v < bv || (v == bv && iv < bi)) { bv = v; bi = iv; }
        }
        g_amin[row0 + tid] = bi;
    }
}

// ---------------------------------------------------------------------------
// Gather + straight-through output + loss partial sums.
// ---------------------------------------------------------------------------
__global__ __launch_bounds__(256) void k_gather(const float* __restrict__ x,
                                                const float* __restrict__ cb,
                                                float* __restrict__ out) {
    int tid = threadIdx.x;
    int row = blockIdx.x * 4 + (tid >> 6);
    int lane = tid & 63;
    int k = g_amin[row];

    float4 xv = *(const float4*)&x[(size_t)row * DD + lane * 4];
    float4 cv = *(const float4*)&cb[(size_t)k * DD + lane * 4];

    float4 o;
    o.x = __fadd_rn(xv.x, __fadd_rn(cv.x, -xv.x));
    o.y = __fadd_rn(xv.y, __fadd_rn(cv.y, -xv.y));
    o.z = __fadd_rn(xv.z, __fadd_rn(cv.z, -xv.z));
    o.w = __fadd_rn(xv.w, __fadd_rn(cv.w, -xv.w));
    *(float4*)&out[(size_t)row * DD + lane * 4] = o;

    float dx = __fadd_rn(xv.x, -cv.x);
    float dy = __fadd_rn(xv.y, -cv.y);
    float dz = __fadd_rn(xv.z, -cv.z);
    float dw = __fadd_rn(xv.w, -cv.w);
    double s = (double)(__fmul_rn(dx, dx)) + (double)(__fmul_rn(dy, dy)) +
               (double)(__fmul_rn(dz, dz)) + (double)(__fmul_rn(dw, dw));

    __shared__ double sred[256];
    sred[tid] = s;
    __syncthreads();
    for (int off = 128; off > 0; off >>= 1) {
        if (tid < off) sred[tid] += sred[tid + off];
        __syncthreads();
    }
    if (tid == 0) atomicAdd(&g_lsum, sred[0]);
}

__global__ void k_final(float* __restrict__ loss_loc) {
    float m = (float)(g_lsum / (double)((long long)NN * DD));
    *loss_loc = __fadd_rn(__fmul_rn(0.25f, m), m);
}

// ---------------------------------------------------------------------------
extern "C" void kernel_launch(void* const* d_in, const int* in_sizes, int n_in,
                              void* d_out, int out_size) {
    const float* x  = (const float*)d_in[0];   // [32768, 256]
    const float* cb = (const float*)d_in[1];   // [2048, 256]
    float* out = (float*)d_out;                // [32768*256] x_quantized + [1] loss

    k_xnorm<<<NN / 256, 256>>>(x);
    k_cnorm<<<KK / 256, 256>>>(cb);
    k_zero<<<1, 32>>>();
    k_dist<<<NN / BM, 256>>>(x, cb);
    k_gather<<<NN / 4, 256>>>(x, cb, out);
    if (out_size > NN * DD) {
        k_final<<<1, 1>>>(out + NN * DD);
    }
}